// round 10
// baseline (speedup 1.0000x reference)
#include <cuda_runtime.h>
#include <cuda_bf16.h>
#include <mma.h>

using namespace nvcuda;

// Problem constants (fixed by the dataset)
#define N_NODES 100000
#define F_DIM   64
#define E_MAX   1600000
#define TOT_CNT (2 * N_NODES)            // 200000 flat counters (pos then neg)
#define SCAN_BLOCKS ((TOT_CNT + 1023) / 1024)   // 196

// Scratch (device globals only — no cudaMalloc allowed).
__device__ __align__(16) float g_sum[2][N_NODES * F_DIM];  // mean features
__device__ __align__(16) int g_cnt [TOT_CNT];       // flat histogram
__device__ __align__(16) int g_off [TOT_CNT + 1];   // flat CSR offsets
__device__ __align__(16) int g_cur [TOT_CNT];       // fill cursors
__device__ int g_part [SCAN_BLOCKS];                // per-block partial sums
__device__ int g_bloff[SCAN_BLOCKS];                // per-block exclusive offset
__device__ int g_srcs [2 * E_MAX];                  // dst-sorted src ids (flat)
__device__ int g_arrive;                            // scan arrival counter
__device__ int g_flag;                              // scan release flag

// ---------------------------------------------------------------------------
// 1) zero histogram counters + scan sync state.
// ---------------------------------------------------------------------------
__global__ void zero_cnt_kernel() {
    unsigned i = blockIdx.x * blockDim.x + threadIdx.x;
    if (i < TOT_CNT) g_cnt[i] = 0;
    if (i == 0) { g_arrive = 0; g_flag = 0; }
}

// ---------------------------------------------------------------------------
// 2) histogram of dst, 4 edges per thread (independent REDs).
// ---------------------------------------------------------------------------
__global__ void hist_kernel(const int* __restrict__ pos_ei,
                            const int* __restrict__ neg_ei, int E) {
    unsigned q = blockIdx.x * blockDim.x + threadIdx.x;   // quad index
    unsigned quads = ((unsigned)E + 3u) / 4u;
    if (q >= 2u * quads) return;
    int set = (q >= quads);
    unsigned e0 = (set ? q - quads : q) * 4u;
    const int* ei = set ? neg_ei : pos_ei;
    int base = set * N_NODES;
    #pragma unroll
    for (int j = 0; j < 4; j++) {
        unsigned e = e0 + j;
        if (e < (unsigned)E) {
            int dst = __ldg(&ei[(unsigned)E + e]);
            atomicAdd(&g_cnt[base + dst], 1);
        }
    }
}

// ---------------------------------------------------------------------------
// 3) single-pass fused scan (196 blocks, one wave -> spin is safe).
// ---------------------------------------------------------------------------
__global__ void scan_fused_kernel() {
    const int b = blockIdx.x, t = threadIdx.x;
    int base = b * 1024 + t * 4;
    int4 v = make_int4(0, 0, 0, 0);
    if (base + 3 < TOT_CNT)      v = *(const int4*)&g_cnt[base];
    else if (base < TOT_CNT) {
        v.x = g_cnt[base];
        if (base + 1 < TOT_CNT) v.y = g_cnt[base + 1];
        if (base + 2 < TOT_CNT) v.z = g_cnt[base + 2];
    }
    int ts = v.x + v.y + v.z + v.w;

    __shared__ int sm[256];
    sm[t] = ts;
    __syncthreads();
    for (int d = 1; d < 256; d <<= 1) {
        int u = (t >= d) ? sm[t - d] : 0;
        __syncthreads();
        sm[t] += u;
        __syncthreads();
    }
    int incl = sm[t];

    if (t == 255) g_part[b] = incl;
    __threadfence();
    __syncthreads();

    if (t == 0) {
        int old = atomicAdd(&g_arrive, 1);
        if (old == SCAN_BLOCKS - 1) {
            int run = 0;
            for (int i = 0; i < SCAN_BLOCKS; i++) {
                int p = g_part[i];
                g_bloff[i] = run;
                run += p;
            }
            g_off[TOT_CNT] = run;
            __threadfence();
            atomicExch(&g_flag, 1);
        }
        while (atomicAdd(&g_flag, 0) == 0) __nanosleep(200);
    }
    __syncthreads();

    int o = g_bloff[b] + incl - ts;
    if (base < TOT_CNT) {
        int o0 = o, o1 = o0 + v.x, o2 = o1 + v.y, o3 = o2 + v.z;
        g_off[base] = o0; g_cur[base] = o0;
        if (base + 1 < TOT_CNT) { g_off[base + 1] = o1; g_cur[base + 1] = o1; }
        if (base + 2 < TOT_CNT) { g_off[base + 2] = o2; g_cur[base + 2] = o2; }
        if (base + 3 < TOT_CNT) { g_off[base + 3] = o3; g_cur[base + 3] = o3; }
    }
}

// ---------------------------------------------------------------------------
// 4) fill: counting sort, 4 edges per thread (4 independent atomic->store
//    chains to hide the 318-cycle ATOMG latency).
// ---------------------------------------------------------------------------
__global__ void fill_kernel(const int* __restrict__ pos_ei,
                            const int* __restrict__ neg_ei, int E) {
    unsigned q = blockIdx.x * blockDim.x + threadIdx.x;
    unsigned quads = ((unsigned)E + 3u) / 4u;
    if (q >= 2u * quads) return;
    int set = (q >= quads);
    unsigned e0 = (set ? q - quads : q) * 4u;
    const int* ei = set ? neg_ei : pos_ei;
    int base = set * N_NODES;

    int src[4], pos[4];
    bool ok[4];
    #pragma unroll
    for (int j = 0; j < 4; j++) {
        unsigned e = e0 + j;
        ok[j] = (e < (unsigned)E);
        if (ok[j]) {
            src[j] = __ldg(&ei[e]);
            int dst = __ldg(&ei[(unsigned)E + e]);
            pos[j] = atomicAdd(&g_cur[base + dst], 1);
        }
    }
    #pragma unroll
    for (int j = 0; j < 4; j++)
        if (ok[j]) g_srcs[pos[j]] = src[j];
}

// ---------------------------------------------------------------------------
// 5) gather: 16 threads per (set,node); 16 independent float4 loads in
//    flight per iteration (256B/thread MLP). Store the MEAN. No atomics.
// ---------------------------------------------------------------------------
__global__ void gather_kernel(const float* __restrict__ x) {
    unsigned idx = blockIdx.x * blockDim.x + threadIdx.x;
    const unsigned per_set = (unsigned)N_NODES * 16u;
    if (idx >= 2u * per_set) return;
    int set = (idx >= per_set);
    unsigned r = set ? idx - per_set : idx;
    unsigned n = r >> 4;
    unsigned c = r & 15u;
    unsigned gid = (unsigned)set * N_NODES + n;

    int beg = g_off[gid];
    int end = g_off[gid + 1];

    float4 a0 = make_float4(0.f,0.f,0.f,0.f), a1 = a0, a2 = a0, a3 = a0;
    int e = beg;
    // 16-deep main loop
    for (; e + 16 <= end; e += 16) {
        int s[16];
        #pragma unroll
        for (int j = 0; j < 16; j++) s[j] = __ldg(&g_srcs[e + j]);
        float4 v[16];
        #pragma unroll
        for (int j = 0; j < 16; j++)
            v[j] = __ldg((const float4*)(x + (unsigned)s[j] * 64u) + c);
        #pragma unroll
        for (int j = 0; j < 16; j += 4) {
            a0.x += v[j].x;   a0.y += v[j].y;   a0.z += v[j].z;   a0.w += v[j].w;
            a1.x += v[j+1].x; a1.y += v[j+1].y; a1.z += v[j+1].z; a1.w += v[j+1].w;
            a2.x += v[j+2].x; a2.y += v[j+2].y; a2.z += v[j+2].z; a2.w += v[j+2].w;
            a3.x += v[j+3].x; a3.y += v[j+3].y; a3.z += v[j+3].z; a3.w += v[j+3].w;
        }
    }
    // 8-deep
    if (e + 8 <= end) {
        int s[8];
        #pragma unroll
        for (int j = 0; j < 8; j++) s[j] = __ldg(&g_srcs[e + j]);
        float4 v[8];
        #pragma unroll
        for (int j = 0; j < 8; j++)
            v[j] = __ldg((const float4*)(x + (unsigned)s[j] * 64u) + c);
        #pragma unroll
        for (int j = 0; j < 8; j += 4) {
            a0.x += v[j].x;   a0.y += v[j].y;   a0.z += v[j].z;   a0.w += v[j].w;
            a1.x += v[j+1].x; a1.y += v[j+1].y; a1.z += v[j+1].z; a1.w += v[j+1].w;
            a2.x += v[j+2].x; a2.y += v[j+2].y; a2.z += v[j+2].z; a2.w += v[j+2].w;
            a3.x += v[j+3].x; a3.y += v[j+3].y; a3.z += v[j+3].z; a3.w += v[j+3].w;
        }
        e += 8;
    }
    // tail
    for (; e < end; e++) {
        int s0 = __ldg(&g_srcs[e]);
        float4 v0 = __ldg((const float4*)(x + (unsigned)s0 * 64u) + c);
        a0.x += v0.x; a0.y += v0.y; a0.z += v0.z; a0.w += v0.w;
    }
    float4 acc;
    acc.x = (a0.x + a1.x) + (a2.x + a3.x);
    acc.y = (a0.y + a1.y) + (a2.y + a3.y);
    acc.z = (a0.z + a1.z) + (a2.z + a3.z);
    acc.w = (a0.w + a1.w) + (a2.w + a3.w);
    float inv = 1.f / (float)max(end - beg, 1);
    acc.x *= inv; acc.y *= inv; acc.z *= inv; acc.w *= inv;
    ((float4*)(g_sum[set] + n * 64u))[c] = acc;
}

// ---------------------------------------------------------------------------
// 6) fused GEMM via tensor cores (3xTF32), A tiles staged in smem.
// ---------------------------------------------------------------------------
__global__ __launch_bounds__(256) void gemm_kernel(
        const float* __restrict__ x,
        const float* __restrict__ Wp,
        const float* __restrict__ Wpc,
        const float* __restrict__ bp,
        const float* __restrict__ Wn,
        const float* __restrict__ Wnc,
        const float* __restrict__ bn,
        float* __restrict__ out) {
    __shared__ float sx [16][68];
    __shared__ float ssp[16][68];
    __shared__ float ssn[16][68];
    __shared__ float smo[8][16][16];

    const int tid  = threadIdx.x;
    const int m0   = blockIdx.x * 16;
    const int w    = tid >> 5;
    const int lane = tid & 31;
    const int side = w >> 2;              // 0 = pos, 1 = neg
    const int n0   = (w & 3) * 16;

    {
        int r  = tid >> 4;
        int ch = tid & 15;
        int grow = m0 + r;
        float4 vx = *((const float4*)(x        + grow * 64) + ch);
        float4 vp = *((const float4*)(g_sum[0] + grow * 64) + ch);
        float4 vn = *((const float4*)(g_sum[1] + grow * 64) + ch);
        int cc = ch * 4;
        sx [r][cc+0] = vx.x; sx [r][cc+1] = vx.y; sx [r][cc+2] = vx.z; sx [r][cc+3] = vx.w;
        ssp[r][cc+0] = vp.x; ssp[r][cc+1] = vp.y; ssp[r][cc+2] = vp.z; ssp[r][cc+3] = vp.w;
        ssn[r][cc+0] = vn.x; ssn[r][cc+1] = vn.y; ssn[r][cc+2] = vn.z; ssn[r][cc+3] = vn.w;
    }
    __syncthreads();

    const float* A1 = side ? &ssn[0][0] : &ssp[0][0];
    const float* W1 = side ? Wn  : Wp;
    const float* W2 = side ? Wnc : Wpc;
    const float* bb = side ? bn  : bp;

    wmma::fragment<wmma::accumulator, 16, 16, 8, float> acc;
    wmma::fill_fragment(acc, 0.0f);

    wmma::fragment<wmma::matrix_a, 16, 16, 8, wmma::precision::tf32, wmma::row_major> af, a_hi, a_lo;
    wmma::fragment<wmma::matrix_b, 16, 16, 8, wmma::precision::tf32, wmma::col_major> bf, b_hi, b_lo;

    #pragma unroll
    for (int k = 0; k < 64; k += 8) {
        wmma::load_matrix_sync(af, A1 + k, 68);
        wmma::load_matrix_sync(bf, W1 + n0 * 64 + k, 64);
        #pragma unroll
        for (int i = 0; i < af.num_elements; i++) {
            float v  = af.x[i];
            float hi = wmma::__float_to_tf32(v);
            a_hi.x[i] = hi;
            a_lo.x[i] = wmma::__float_to_tf32(v - hi);
        }
        #pragma unroll
        for (int i = 0; i < bf.num_elements; i++) {
            float v  = bf.x[i];
            float hi = wmma::__float_to_tf32(v);
            b_hi.x[i] = hi;
            b_lo.x[i] = wmma::__float_to_tf32(v - hi);
        }
        wmma::mma_sync(acc, a_hi, b_hi, acc);
        wmma::mma_sync(acc, a_hi, b_lo, acc);
        wmma::mma_sync(acc, a_lo, b_hi, acc);

        wmma::load_matrix_sync(af, &sx[0][0] + k, 68);
        wmma::load_matrix_sync(bf, W2 + n0 * 64 + k, 64);
        #pragma unroll
        for (int i = 0; i < af.num_elements; i++) {
            float v  = af.x[i];
            float hi = wmma::__float_to_tf32(v);
            a_hi.x[i] = hi;
            a_lo.x[i] = wmma::__float_to_tf32(v - hi);
        }
        #pragma unroll
        for (int i = 0; i < bf.num_elements; i++) {
            float v  = bf.x[i];
            float hi = wmma::__float_to_tf32(v);
            b_hi.x[i] = hi;
            b_lo.x[i] = wmma::__float_to_tf32(v - hi);
        }
        wmma::mma_sync(acc, a_hi, b_hi, acc);
        wmma::mma_sync(acc, a_hi, b_lo, acc);
        wmma::mma_sync(acc, a_lo, b_hi, acc);
    }

    wmma::store_matrix_sync(&smo[w][0][0], acc, 16, wmma::mem_row_major);
    __syncwarp();

    #pragma unroll
    for (int t = 0; t < 8; t++) {
        int elem = lane + t * 32;
        int i = elem >> 4;
        int j = elem & 15;
        float val = smo[w][i][j] + __ldg(&bb[n0 + j]);
        out[(m0 + i) * 128 + side * 64 + n0 + j] = val;
    }
}

// ---------------------------------------------------------------------------
extern "C" void kernel_launch(void* const* d_in, const int* in_sizes, int n_in,
                              void* d_out, int out_size) {
    const float* x   = (const float*)d_in[0];
    const int*   pe  = (const int*)d_in[1];   // int32 (JAX downcasts int64)
    const int*   ne  = (const int*)d_in[2];
    const float* Wp  = (const float*)d_in[3];
    const float* Wpc = (const float*)d_in[4];
    const float* bp  = (const float*)d_in[5];
    const float* Wn  = (const float*)d_in[6];
    const float* Wnc = (const float*)d_in[7];
    const float* bn  = (const float*)d_in[8];
    float* out = (float*)d_out;

    int E = in_sizes[1] / 2;   // edge_index is [2, E]
    unsigned quads = ((unsigned)E + 3u) / 4u;

    zero_cnt_kernel<<<(TOT_CNT + 255) / 256, 256>>>();
    hist_kernel<<<(2 * quads + 255) / 256, 256>>>(pe, ne, E);
    scan_fused_kernel<<<SCAN_BLOCKS, 256>>>();
    fill_kernel<<<(2 * quads + 255) / 256, 256>>>(pe, ne, E);
    gather_kernel<<<(2 * N_NODES * 16 + 255) / 256, 256>>>(x);
    gemm_kernel<<<N_NODES / 16, 256>>>(x, Wp, Wpc, bp, Wn, Wnc, bn, out);
}